// round 14
// baseline (speedup 1.0000x reference)
#include <cuda_runtime.h>
#include <cstdint>
#include <cstddef>

// ---------------------------------------------------------------------------
// Problem dims
// ---------------------------------------------------------------------------
#define B_DIM   8192
#define IN_DIM  4096
#define OUT_DIM 2048

// GEMM tiling (BN=128 saturates the IMMA pipe at 94% of the rt=16cyc floor)
#define BM 128
#define BN 128
#define BK 64
#define KSTEPS (IN_DIM / BK)        // 64
#define NBUF 4                      // 4 smem buffers, prefetch depth 3

// Smem: rows padded to 80B so 4B fragment loads are bank-conflict-free
#define ROW_STRIDE 80
#define A_BYTES (BM * ROW_STRIDE)   // 10240
#define B_BYTES (BN * ROW_STRIDE)   // 10240
#define STAGE_BYTES (A_BYTES + B_BYTES)          // 20480
#define SMEM_SCALE 0                              // 128 floats
#define SMEM_AB    1024
#define SMEM_TOTAL (SMEM_AB + NBUF * STAGE_BYTES) // 82944

// Merged quantize kernel geometry
#define XQ_BLOCKS 8192              // X part: 8192 blocks x 256 thr x 4 u32
#define XQ_STRIDE ((size_t)XQ_BLOCKS * 256)
#define WQ_BLOCKS ((OUT_DIM / 32) * (IN_DIM / 32))   // 8192

// ---------------------------------------------------------------------------
// Scratch (device globals; referenced only from device code)
// ---------------------------------------------------------------------------
__device__ __align__(16) int8_t g_Xb[(size_t)B_DIM * IN_DIM];    // sign(X), K-major
__device__ __align__(16) int8_t g_Wb[(size_t)OUT_DIM * IN_DIM];  // sign(W)^T, K-major

// ---------------------------------------------------------------------------
// Helpers (sm_80-compatible PTX only)
// ---------------------------------------------------------------------------
__device__ __forceinline__ uint32_t smem_u32(const void* p) {
    uint32_t a;
    asm("{ .reg .u64 t; cvta.to.shared.u64 t, %1; cvt.u32.u64 %0, t; }" : "=r"(a) : "l"(p));
    return a;
}
__device__ __forceinline__ void cp_async16(uint32_t dst, const void* src) {
    asm volatile("cp.async.cg.shared.global [%0], [%1], 16;" :: "r"(dst), "l"(src) : "memory");
}
__device__ __forceinline__ void mma_s8(int* c, const uint32_t* a, const uint32_t* b) {
    asm volatile(
        "mma.sync.aligned.m16n8k32.row.col.s32.s8.s8.s32 "
        "{%0,%1,%2,%3}, {%4,%5,%6,%7}, {%8,%9}, {%0,%1,%2,%3};"
        : "+r"(c[0]), "+r"(c[1]), "+r"(c[2]), "+r"(c[3])
        : "r"(a[0]), "r"(a[1]), "r"(a[2]), "r"(a[3]), "r"(b[0]), "r"(b[1]));
}
__device__ __forceinline__ uint32_t sign_byte(uint32_t fbits) {
    // 0x01 for >=0, 0xFF (-1) for negative
    return 0x01u ^ (0xFEu & (uint32_t)(-(int32_t)(fbits >> 31)));
}
__device__ __forceinline__ uint4 ldcs4(const uint4* p) {
    uint4 v;
    asm volatile("ld.global.cs.v4.u32 {%0,%1,%2,%3}, [%4];"
                 : "=r"(v.x), "=r"(v.y), "=r"(v.z), "=r"(v.w) : "l"(p));
    return v;
}
__device__ __forceinline__ uint32_t pack_sign(uint4 v) {
    return sign_byte(v.x) | (sign_byte(v.y) << 8)
         | (sign_byte(v.z) << 16) | (sign_byte(v.w) << 24);
}

// ---------------------------------------------------------------------------
// Kernel 1 (merged): quantize X (blocks [0, XQ_BLOCKS)) and quantize+
// transpose W (blocks [XQ_BLOCKS, XQ_BLOCKS+WQ_BLOCKS)).
//   X: -> int8 {+1,-1}, [B, IN] K-major; streaming loads, MLP=4.
//   W[IN,OUT] -> Wb[OUT,IN] int8 {+1,-1} via 32x32 smem transpose.
// ---------------------------------------------------------------------------
__global__ void __launch_bounds__(256) quant_kernel(const float* __restrict__ X,
                                                    const float* __restrict__ W) {
    __shared__ uint8_t tile[32][33];
    if (blockIdx.x < XQ_BLOCKS) {
        size_t i = (size_t)blockIdx.x * 256 + threadIdx.x;
        const uint4* Xv = reinterpret_cast<const uint4*>(X);
        uint4 v0 = ldcs4(Xv + i);
        uint4 v1 = ldcs4(Xv + i + XQ_STRIDE);
        uint4 v2 = ldcs4(Xv + i + 2 * XQ_STRIDE);
        uint4 v3 = ldcs4(Xv + i + 3 * XQ_STRIDE);
        uint32_t* out = reinterpret_cast<uint32_t*>(g_Xb);
        out[i]                 = pack_sign(v0);
        out[i + XQ_STRIDE]     = pack_sign(v1);
        out[i + 2 * XQ_STRIDE] = pack_sign(v2);
        out[i + 3 * XQ_STRIDE] = pack_sign(v3);
    } else {
        int wb = blockIdx.x - XQ_BLOCKS;
        int n0 = (wb & 63) * 32, k0 = (wb >> 6) * 32;
        int tx = threadIdx.x & 31, ty = threadIdx.x >> 5;
#pragma unroll
        for (int j = 0; j < 4; j++) {
            int kk = ty + j * 8;
            tile[kk][tx] = (uint8_t)sign_byte(
                __float_as_uint(W[(size_t)(k0 + kk) * OUT_DIM + n0 + tx]));
        }
        __syncthreads();
        int t = threadIdx.x;
        int nn = t >> 3;            // 0..31
        int kk = (t & 7) * 4;       // 0..28
        uint32_t p = (uint32_t)tile[kk + 0][nn]
                   | ((uint32_t)tile[kk + 1][nn] << 8)
                   | ((uint32_t)tile[kk + 2][nn] << 16)
                   | ((uint32_t)tile[kk + 3][nn] << 24);
        *reinterpret_cast<uint32_t*>(&g_Wb[(size_t)(n0 + nn) * IN_DIM + k0 + kk]) = p;
    }
}

// ---------------------------------------------------------------------------
// Kernel 2: int8 mma.sync GEMM + fused scale epilogue (BM=128 x BN=128).
// Fill for stage ks+3 is issued immediately after the barrier, before the
// MMA work, so cp.async latency overlaps the whole MMA block.
//   D[m,n] = sum_k Xb[m,k]*Wb[n,k] (exact int); out = float(D) * scale[n]
// ---------------------------------------------------------------------------
__global__ void __launch_bounds__(256, 2) gemm_kernel(
    const float* __restrict__ alpha, const float* __restrict__ betta,
    const float* __restrict__ gamma, float* __restrict__ out)
{
    extern __shared__ char smem[];
    uint32_t sb = smem_u32(smem);
    int tid = threadIdx.x, wid = tid >> 5, lane = tid & 31;
    int warp_m = wid >> 2, warp_n = wid & 3;        // 2 x 4 warp grid
    int g = lane >> 2, q = lane & 3;
    int n0 = blockIdx.x * BN, m0 = blockIdx.y * BM;

    if (tid < BN) {   // per-column scale
        int n = n0 + tid;
        float s = fmaxf(__ldg(alpha), 0.f) * fmaxf(__ldg(&betta[n >> 6]), 0.f)
                * fmaxf(__ldg(&gamma[n & 63]), 0.f);
        reinterpret_cast<float*>(smem + SMEM_SCALE)[tid] = s;
    }

    // cp.async fill: 1024 x 16B chunks per stage (512 A + 512 B), 4 per thread
    auto fill = [&](int ks) {
        uint32_t dst = sb + SMEM_AB + (ks & (NBUF - 1)) * STAGE_BYTES;
        size_t ksrc = (size_t)ks * BK;
#pragma unroll
        for (int i = 0; i < 4; i++) {
            int c = tid + i * 256;
            if (c < 512) {
                int row = c >> 2, q16 = c & 3;
                cp_async16(dst + row * ROW_STRIDE + q16 * 16,
                           g_Xb + (size_t)(m0 + row) * IN_DIM + ksrc + q16 * 16);
            } else {
                int c2 = c - 512;
                int row = c2 >> 2, q16 = c2 & 3;
                cp_async16(dst + A_BYTES + row * ROW_STRIDE + q16 * 16,
                           g_Wb + (size_t)(n0 + row) * IN_DIM + ksrc + q16 * 16);
            }
        }
        asm volatile("cp.async.commit_group;" ::: "memory");
    };

    int acc[4][4][4];
#pragma unroll
    for (int mi = 0; mi < 4; mi++)
#pragma unroll
        for (int nj = 0; nj < 4; nj++)
#pragma unroll
            for (int r = 0; r < 4; r++) acc[mi][nj][r] = 0;

    fill(0); fill(1); fill(2);

    for (int ks = 0; ks < KSTEPS; ks++) {
        asm volatile("cp.async.wait_group 2;" ::: "memory");   // stage ks resident
        __syncthreads();

        // Fill early: buffer (ks+3)&3 == (ks-1)&3 was fully consumed in
        // iteration ks-1, and the barrier above orders that consumption.
        if (ks + 3 < KSTEPS) fill(ks + 3);
        else asm volatile("cp.async.commit_group;" ::: "memory");  // uniform accounting

        const char* sA = smem + SMEM_AB + (ks & (NBUF - 1)) * STAGE_BYTES;
        const char* sB = sA + A_BYTES;
#pragma unroll
        for (int kk = 0; kk < 2; kk++) {                       // two k32 steps per BK=64
            int ko = kk * 32;
            uint32_t a[4][4], b[4][2];
#pragma unroll
            for (int mi = 0; mi < 4; mi++) {
                const char* pa = sA + (warp_m * 64 + mi * 16 + g) * ROW_STRIDE + q * 4 + ko;
                a[mi][0] = *reinterpret_cast<const uint32_t*>(pa);
                a[mi][1] = *reinterpret_cast<const uint32_t*>(pa + 8 * ROW_STRIDE);
                a[mi][2] = *reinterpret_cast<const uint32_t*>(pa + 16);
                a[mi][3] = *reinterpret_cast<const uint32_t*>(pa + 8 * ROW_STRIDE + 16);
            }
#pragma unroll
            for (int nj = 0; nj < 4; nj++) {
                const char* pb = sB + (warp_n * 32 + nj * 8 + g) * ROW_STRIDE + q * 4 + ko;
                b[nj][0] = *reinterpret_cast<const uint32_t*>(pb);
                b[nj][1] = *reinterpret_cast<const uint32_t*>(pb + 16);
            }
#pragma unroll
            for (int mi = 0; mi < 4; mi++)
#pragma unroll
                for (int nj = 0; nj < 4; nj++)
                    mma_s8(acc[mi][nj], a[mi], b[nj]);
        }
    }

    __syncthreads();
    const float* sc = reinterpret_cast<const float*>(smem + SMEM_SCALE);
#pragma unroll
    for (int mi = 0; mi < 4; mi++) {
        int r0 = m0 + warp_m * 64 + mi * 16 + g;
#pragma unroll
        for (int nj = 0; nj < 4; nj++) {
            int col = warp_n * 32 + nj * 8 + 2 * q;
            float s0 = sc[col], s1 = sc[col + 1];
            float2 v0 = make_float2((float)acc[mi][nj][0] * s0, (float)acc[mi][nj][1] * s1);
            float2 v1 = make_float2((float)acc[mi][nj][2] * s0, (float)acc[mi][nj][3] * s1);
            *reinterpret_cast<float2*>(out + (size_t)r0 * OUT_DIM + n0 + col) = v0;
            *reinterpret_cast<float2*>(out + (size_t)(r0 + 8) * OUT_DIM + n0 + col) = v1;
        }
    }
}

// ---------------------------------------------------------------------------
// Launch
// ---------------------------------------------------------------------------
extern "C" void kernel_launch(void* const* d_in, const int* in_sizes, int n_in,
                              void* d_out, int out_size) {
    const float *X = nullptr, *W = nullptr, *alpha = nullptr, *betta = nullptr, *gamma = nullptr;
    for (int i = 0; i < n_in; i++) {
        switch (in_sizes[i]) {
            case B_DIM * IN_DIM:   X     = (const float*)d_in[i]; break;  // 33554432
            case IN_DIM * OUT_DIM: W     = (const float*)d_in[i]; break;  // 8388608
            case 1:                alpha = (const float*)d_in[i]; break;
            case 32:               betta = (const float*)d_in[i]; break;
            case 64:               gamma = (const float*)d_in[i]; break;
        }
    }
    cudaFuncSetAttribute(gemm_kernel, cudaFuncAttributeMaxDynamicSharedMemorySize, SMEM_TOTAL);

    quant_kernel<<<XQ_BLOCKS + WQ_BLOCKS, 256>>>(X, W);
    gemm_kernel<<<dim3(OUT_DIM / BN, B_DIM / BM), 256, SMEM_TOTAL>>>(
        alpha, betta, gamma, (float*)d_out);
}

// round 16
// speedup vs baseline: 1.1844x; 1.1844x over previous
#include <cuda_runtime.h>
#include <cstdint>
#include <cstddef>

// ---------------------------------------------------------------------------
// Problem dims
// ---------------------------------------------------------------------------
#define B_DIM   8192
#define IN_DIM  4096
#define OUT_DIM 2048

// GEMM tiling
#define BM 128
#define BN 128
#define BK 64
#define KSTEPS (IN_DIM / BK)        // 64
#define NBUF 4                      // 4 smem buffers, prefetch depth 3

// Smem: rows padded to 80B. 80 = 5*16 and 5 is odd, so 8 consecutive rows hit
// 8 distinct 16B slots mod 128B -> conflict-free for both LDS.32 and ldmatrix.
#define ROW_STRIDE 80
#define A_BYTES (BM * ROW_STRIDE)   // 10240
#define B_BYTES (BN * ROW_STRIDE)   // 10240
#define STAGE_BYTES (A_BYTES + B_BYTES)          // 20480
#define SMEM_SCALE 0                              // 128 floats
#define SMEM_AB    1024
#define SMEM_TOTAL (SMEM_AB + NBUF * STAGE_BYTES) // 82944

// Merged quantize kernel geometry
#define XQ_BLOCKS 8192              // X part: 8192 blocks x 256 thr x 4 u32
#define XQ_STRIDE ((size_t)XQ_BLOCKS * 256)
#define WQ_BLOCKS ((OUT_DIM / 32) * (IN_DIM / 32))   // 8192

// ---------------------------------------------------------------------------
// Scratch (device globals; referenced only from device code)
// ---------------------------------------------------------------------------
__device__ __align__(16) int8_t g_Xb[(size_t)B_DIM * IN_DIM];    // sign(X), K-major
__device__ __align__(16) int8_t g_Wb[(size_t)OUT_DIM * IN_DIM];  // sign(W)^T, K-major

// ---------------------------------------------------------------------------
// Helpers (sm_80-compatible PTX only)
// ---------------------------------------------------------------------------
__device__ __forceinline__ uint32_t smem_u32(const void* p) {
    uint32_t a;
    asm("{ .reg .u64 t; cvta.to.shared.u64 t, %1; cvt.u32.u64 %0, t; }" : "=r"(a) : "l"(p));
    return a;
}
__device__ __forceinline__ void cp_async16(uint32_t dst, const void* src) {
    asm volatile("cp.async.cg.shared.global [%0], [%1], 16;" :: "r"(dst), "l"(src) : "memory");
}
__device__ __forceinline__ void mma_s8(int* c, const uint32_t* a, const uint32_t* b) {
    asm volatile(
        "mma.sync.aligned.m16n8k32.row.col.s32.s8.s8.s32 "
        "{%0,%1,%2,%3}, {%4,%5,%6,%7}, {%8,%9}, {%0,%1,%2,%3};"
        : "+r"(c[0]), "+r"(c[1]), "+r"(c[2]), "+r"(c[3])
        : "r"(a[0]), "r"(a[1]), "r"(a[2]), "r"(a[3]), "r"(b[0]), "r"(b[1]));
}
#define LDSM_X4(r0, r1, r2, r3, addr) \
    asm volatile("ldmatrix.sync.aligned.m8n8.x4.shared.b16 {%0,%1,%2,%3}, [%4];" \
                 : "=r"(r0), "=r"(r1), "=r"(r2), "=r"(r3) : "r"(addr))
__device__ __forceinline__ uint32_t sign_byte(uint32_t fbits) {
    // 0x01 for >=0, 0xFF (-1) for negative
    return 0x01u ^ (0xFEu & (uint32_t)(-(int32_t)(fbits >> 31)));
}
__device__ __forceinline__ uint4 ldcs4(const uint4* p) {
    uint4 v;
    asm volatile("ld.global.cs.v4.u32 {%0,%1,%2,%3}, [%4];"
                 : "=r"(v.x), "=r"(v.y), "=r"(v.z), "=r"(v.w) : "l"(p));
    return v;
}
__device__ __forceinline__ uint32_t pack_sign(uint4 v) {
    return sign_byte(v.x) | (sign_byte(v.y) << 8)
         | (sign_byte(v.z) << 16) | (sign_byte(v.w) << 24);
}

// ---------------------------------------------------------------------------
// Kernel 1 (merged): quantize X (blocks [0, XQ_BLOCKS)) and quantize+
// transpose W (blocks [XQ_BLOCKS, XQ_BLOCKS+WQ_BLOCKS)).
// ---------------------------------------------------------------------------
__global__ void __launch_bounds__(256) quant_kernel(const float* __restrict__ X,
                                                    const float* __restrict__ W) {
    __shared__ uint8_t tile[32][33];
    if (blockIdx.x < XQ_BLOCKS) {
        size_t i = (size_t)blockIdx.x * 256 + threadIdx.x;
        const uint4* Xv = reinterpret_cast<const uint4*>(X);
        uint4 v0 = ldcs4(Xv + i);
        uint4 v1 = ldcs4(Xv + i + XQ_STRIDE);
        uint4 v2 = ldcs4(Xv + i + 2 * XQ_STRIDE);
        uint4 v3 = ldcs4(Xv + i + 3 * XQ_STRIDE);
        uint32_t* out = reinterpret_cast<uint32_t*>(g_Xb);
        out[i]                 = pack_sign(v0);
        out[i + XQ_STRIDE]     = pack_sign(v1);
        out[i + 2 * XQ_STRIDE] = pack_sign(v2);
        out[i + 3 * XQ_STRIDE] = pack_sign(v3);
    } else {
        int wb = blockIdx.x - XQ_BLOCKS;
        int n0 = (wb & 63) * 32, k0 = (wb >> 6) * 32;
        int tx = threadIdx.x & 31, ty = threadIdx.x >> 5;
#pragma unroll
        for (int j = 0; j < 4; j++) {
            int kk = ty + j * 8;
            tile[kk][tx] = (uint8_t)sign_byte(
                __float_as_uint(W[(size_t)(k0 + kk) * OUT_DIM + n0 + tx]));
        }
        __syncthreads();
        int t = threadIdx.x;
        int nn = t >> 3;            // 0..31
        int kk = (t & 7) * 4;       // 0..28
        uint32_t p = (uint32_t)tile[kk + 0][nn]
                   | ((uint32_t)tile[kk + 1][nn] << 8)
                   | ((uint32_t)tile[kk + 2][nn] << 16)
                   | ((uint32_t)tile[kk + 3][nn] << 24);
        *reinterpret_cast<uint32_t*>(&g_Wb[(size_t)(n0 + nn) * IN_DIM + k0 + kk]) = p;
    }
}

// ---------------------------------------------------------------------------
// Kernel 2: int8 mma.sync GEMM, fragments via ldmatrix.x4 (12 LDSM/warp/iter
// instead of 48 scalar LDS -> 4x fewer issue slots + scoreboard events).
//   D[m,n] = sum_k Xb[m,k]*Wb[n,k] (exact int); out = float(D) * scale[n]
// ---------------------------------------------------------------------------
__global__ void __launch_bounds__(256, 2) gemm_kernel(
    const float* __restrict__ alpha, const float* __restrict__ betta,
    const float* __restrict__ gamma, float* __restrict__ out)
{
    extern __shared__ char smem[];
    uint32_t sb = smem_u32(smem);
    int tid = threadIdx.x, wid = tid >> 5, lane = tid & 31;
    int warp_m = wid >> 2, warp_n = wid & 3;        // 2 x 4 warp grid
    int g = lane >> 2, q = lane & 3;
    int n0 = blockIdx.x * BN, m0 = blockIdx.y * BM;

    if (tid < BN) {   // per-column scale
        int n = n0 + tid;
        float s = fmaxf(__ldg(alpha), 0.f) * fmaxf(__ldg(&betta[n >> 6]), 0.f)
                * fmaxf(__ldg(&gamma[n & 63]), 0.f);
        reinterpret_cast<float*>(smem + SMEM_SCALE)[tid] = s;
    }

    // ldmatrix per-lane addressing (within a 16-row x 32B tile):
    //   A x4: matrix = lane>>3; row = (matrix&1)*8 + (lane&7); khalf = (matrix>>1)*16
    //   B x4 (two 8-row n-tiles): ntile = (lane>>4); khalf = ((lane>>3)&1)*16; row = lane&7
    int a_row   = ((lane >> 3) & 1) * 8 + (lane & 7);
    int a_khalf = (lane >> 4) * 16;
    int b_tile  = (lane >> 4);                 // 0 or 1 within the nj pair
    int b_khalf = ((lane >> 3) & 1) * 16;
    int b_row   = lane & 7;

    // cp.async fill: 1024 x 16B chunks per stage (512 A + 512 B), 4 per thread
    auto fill = [&](int ks) {
        uint32_t dst = sb + SMEM_AB + (ks & (NBUF - 1)) * STAGE_BYTES;
        size_t ksrc = (size_t)ks * BK;
#pragma unroll
        for (int i = 0; i < 4; i++) {
            int c = tid + i * 256;
            if (c < 512) {
                int row = c >> 2, q16 = c & 3;
                cp_async16(dst + row * ROW_STRIDE + q16 * 16,
                           g_Xb + (size_t)(m0 + row) * IN_DIM + ksrc + q16 * 16);
            } else {
                int c2 = c - 512;
                int row = c2 >> 2, q16 = c2 & 3;
                cp_async16(dst + A_BYTES + row * ROW_STRIDE + q16 * 16,
                           g_Wb + (size_t)(n0 + row) * IN_DIM + ksrc + q16 * 16);
            }
        }
        asm volatile("cp.async.commit_group;" ::: "memory");
    };

    int acc[4][4][4];
#pragma unroll
    for (int mi = 0; mi < 4; mi++)
#pragma unroll
        for (int nj = 0; nj < 4; nj++)
#pragma unroll
            for (int r = 0; r < 4; r++) acc[mi][nj][r] = 0;

    fill(0); fill(1); fill(2);

    for (int ks = 0; ks < KSTEPS; ks++) {
        asm volatile("cp.async.wait_group 2;" ::: "memory");   // stage ks resident
        __syncthreads();

        uint32_t sAu = sb + SMEM_AB + (ks & (NBUF - 1)) * STAGE_BYTES;
        uint32_t sBu = sAu + A_BYTES;
        // Per-warp per-lane base addresses for this stage
        uint32_t aBase = sAu + (uint32_t)(warp_m * 64 + a_row) * ROW_STRIDE + a_khalf;
        uint32_t bBase = sBu + (uint32_t)(warp_n * 32 + b_tile * 8 + b_row) * ROW_STRIDE + b_khalf;
#pragma unroll
        for (int kk = 0; kk < 2; kk++) {                       // two k32 steps per BK=64
            int ko = kk * 32;
            uint32_t a[4][4], b[4][2];
#pragma unroll
            for (int mi = 0; mi < 4; mi++)
                LDSM_X4(a[mi][0], a[mi][1], a[mi][2], a[mi][3],
                        aBase + (uint32_t)(mi * 16) * ROW_STRIDE + ko);
#pragma unroll
            for (int njp = 0; njp < 2; njp++)
                LDSM_X4(b[njp * 2][0], b[njp * 2][1], b[njp * 2 + 1][0], b[njp * 2 + 1][1],
                        bBase + (uint32_t)(njp * 16) * ROW_STRIDE + ko);
#pragma unroll
            for (int mi = 0; mi < 4; mi++)
#pragma unroll
                for (int nj = 0; nj < 4; nj++)
                    mma_s8(acc[mi][nj], a[mi], b[nj]);
        }
        // Fill-late (measured faster than fill-early in round 14):
        // buffer (ks+3)&3 held stage ks-1, consumed before the barrier above.
        if (ks + 3 < KSTEPS) fill(ks + 3);
        else asm volatile("cp.async.commit_group;" ::: "memory");  // uniform accounting
    }

    __syncthreads();
    const float* sc = reinterpret_cast<const float*>(smem + SMEM_SCALE);
#pragma unroll
    for (int mi = 0; mi < 4; mi++) {
        int r0 = m0 + warp_m * 64 + mi * 16 + g;
#pragma unroll
        for (int nj = 0; nj < 4; nj++) {
            int col = warp_n * 32 + nj * 8 + 2 * q;
            float s0 = sc[col], s1 = sc[col + 1];
            float2 v0 = make_float2((float)acc[mi][nj][0] * s0, (float)acc[mi][nj][1] * s1);
            float2 v1 = make_float2((float)acc[mi][nj][2] * s0, (float)acc[mi][nj][3] * s1);
            *reinterpret_cast<float2*>(out + (size_t)r0 * OUT_DIM + n0 + col) = v0;
            *reinterpret_cast<float2*>(out + (size_t)(r0 + 8) * OUT_DIM + n0 + col) = v1;
        }
    }
}

// ---------------------------------------------------------------------------
// Launch
// ---------------------------------------------------------------------------
extern "C" void kernel_launch(void* const* d_in, const int* in_sizes, int n_in,
                              void* d_out, int out_size) {
    const float *X = nullptr, *W = nullptr, *alpha = nullptr, *betta = nullptr, *gamma = nullptr;
    for (int i = 0; i < n_in; i++) {
        switch (in_sizes[i]) {
            case B_DIM * IN_DIM:   X     = (const float*)d_in[i]; break;  // 33554432
            case IN_DIM * OUT_DIM: W     = (const float*)d_in[i]; break;  // 8388608
            case 1:                alpha = (const float*)d_in[i]; break;
            case 32:               betta = (const float*)d_in[i]; break;
            case 64:               gamma = (const float*)d_in[i]; break;
        }
    }
    cudaFuncSetAttribute(gemm_kernel, cudaFuncAttributeMaxDynamicSharedMemorySize, SMEM_TOTAL);

    quant_kernel<<<XQ_BLOCKS + WQ_BLOCKS, 256>>>(X, W);
    gemm_kernel<<<dim3(OUT_DIM / BN, B_DIM / BM), 256, SMEM_TOTAL>>>(
        alpha, betta, gamma, (float*)d_out);
}